// round 15
// baseline (speedup 1.0000x reference)
#include <cuda_runtime.h>
#include <cuda_fp16.h>
#include <cstdint>

#define Nn   100000
#define Ee   1600000
#define Bb   2
#define FIN  116
#define EMBD 12
#define Hh   128
#define NS2  8           // K chunks of 16 (K padded to 128)
#define NC   128         // accumulator copies
#define NPB  64          // nodes per agg block (16 per warp)
#define NSB  98          // scan blocks (ceil(100000/1024))

#define QSCALE (127.0f / 8.0f)
#define QINV   (8.0f / 127.0f)

// -------- scratch (static device globals) --------
__device__ char  g_x8[(size_t)Nn * 256];   // [n][2h+b] int8 quantized xw1: 25.6 MB
__device__ int   g_cnt[Nn];
__device__ int   g_cursor[Nn];
__device__ float g_dis[Nn];
__device__ float g_tsum[Nn];
__device__ int   g_rowstart[Nn + 1];
__device__ int   g_bsum[NSB];
__device__ int   g_csrc[Ee];               // bits[0:17)=src, bits[17:32)=fp16 bits of dis[src]
__device__ float g_T[8 * Hh];
__device__ float g_acc[NC * 256];
__device__ uint32_t g_W1p[64][Hh];         // [kpair][h] fp16x2 packed (low half = even k)

// -------- host-side stream/event resources (created once at load; no device alloc) --------
static cudaStream_t g_s2;
static cudaEvent_t  g_e0, g_e1;
static struct SideStreamInit {
    SideStreamInit() {
        cudaStreamCreateWithFlags(&g_s2, cudaStreamNonBlocking);
        cudaEventCreateWithFlags(&g_e0, cudaEventDisableTiming);
        cudaEventCreateWithFlags(&g_e1, cudaEventDisableTiming);
    }
} g_ssi;

// -------- small helpers --------
__device__ __forceinline__ uint32_t packh(float lo, float hi) {
    __half2 h = __floats2half2_rn(lo, hi);
    return *(uint32_t*)&h;
}
__device__ __forceinline__ void cp16(uint32_t dst, const void* src, bool pred) {
    int sz = pred ? 16 : 0;
    asm volatile("cp.async.cg.shared.global [%0], [%1], 16, %2;\n" :: "r"(dst), "l"(src), "r"(sz));
}
#define CP_COMMIT() asm volatile("cp.async.commit_group;\n" ::: "memory")
#define CP_WAIT1()  asm volatile("cp.async.wait_group 1;\n" ::: "memory")

#define MMA_F16(Cr, Ar, B0, B1)                                               \
    asm volatile("mma.sync.aligned.m16n8k16.row.col.f32.f16.f16.f32 "         \
                 "{%0,%1,%2,%3},{%4,%5,%6,%7},{%8,%9},{%0,%1,%2,%3};"         \
                 : "+f"(Cr[0]), "+f"(Cr[1]), "+f"(Cr[2]), "+f"(Cr[3])         \
                 : "r"(Ar[0]), "r"(Ar[1]), "r"(Ar[2]), "r"(Ar[3]),            \
                   "r"(B0), "r"(B1))

__device__ __forceinline__ char quant8(float v) {
    int q = __float2int_rn(v * QSCALE);
    q = max(-127, min(127, q));
    return (char)q;
}
__device__ __forceinline__ __half2 u2h2(uint32_t u) {
    __half2_raw r; r.x = (unsigned short)(u & 0xffff); r.y = (unsigned short)(u >> 16);
    return r;
}

// -------- prep kernels --------
__global__ void k_zero() {
    int i = blockIdx.x * blockDim.x + threadIdx.x;
    int stride = gridDim.x * blockDim.x;
    for (int j = i; j < Nn; j += stride) g_cnt[j] = 0;
    for (int j = i; j < NC * 256; j += stride) g_acc[j] = 0.f;
}

__global__ void k_hist(const int* __restrict__ dst) {
    int i = blockIdx.x * blockDim.x + threadIdx.x;
    int stride = gridDim.x * blockDim.x;
    for (int e = i; e < Ee; e += stride) atomicAdd(&g_cnt[dst[e]], 1);
}

// ---- 3-phase parallel scan; A computes dis and zeroes tsum; C also seeds cursor ----
__global__ void k_scanA() {
    __shared__ int sd[1024];
    int t = threadIdx.x;
    int idx = blockIdx.x * 1024 + t;
    int v = (idx < Nn) ? g_cnt[idx] : 0;
    sd[t] = v;
    __syncthreads();
    for (int off = 1; off < 1024; off <<= 1) {
        int x = (t >= off) ? sd[t - off] : 0;
        __syncthreads();
        sd[t] += x;
        __syncthreads();
    }
    if (idx < Nn) {
        g_rowstart[idx] = sd[t] - v;   // block-local exclusive
        g_dis[idx] = rsqrtf((float)v + 1.0f);
        g_tsum[idx] = 0.f;
    }
    if (t == 1023) g_bsum[blockIdx.x] = sd[1023];
}

__global__ void k_scanB() {
    int l = threadIdx.x;   // 32 threads
    int base = 4 * l;
    int v0 = (base + 0 < NSB) ? g_bsum[base + 0] : 0;
    int v1 = (base + 1 < NSB) ? g_bsum[base + 1] : 0;
    int v2 = (base + 2 < NSB) ? g_bsum[base + 2] : 0;
    int v3 = (base + 3 < NSB) ? g_bsum[base + 3] : 0;
    int t0 = v0, t1 = t0 + v1, t2 = t1 + v2, tot = t2 + v3;
    int incl = tot;
    #pragma unroll
    for (int off = 1; off < 32; off <<= 1) {
        int y = __shfl_up_sync(0xffffffffu, incl, off);
        if (l >= off) incl += y;
    }
    int excl = incl - tot;
    if (base + 0 < NSB) g_bsum[base + 0] = excl;
    if (base + 1 < NSB) g_bsum[base + 1] = excl + t0;
    if (base + 2 < NSB) g_bsum[base + 2] = excl + t1;
    if (base + 3 < NSB) g_bsum[base + 3] = excl + t2;
    if (l == 31) g_rowstart[Nn] = incl;
}

__global__ void k_scanC() {
    int t = threadIdx.x;
    int idx = blockIdx.x * 1024 + t;
    if (idx < Nn) {
        int rs = g_rowstart[idx] + g_bsum[blockIdx.x];
        g_rowstart[idx] = rs;
        g_cursor[idx] = rs;     // scatter bumps cursor directly
    }
}

// scatter CSR col (src + fp16 dis[src] in top 15 bits) + fused tsum accumulation
__global__ void k_scatter(const int* __restrict__ src, const int* __restrict__ dst) {
    int i = blockIdx.x * blockDim.x + threadIdx.x;
    int stride = gridDim.x * blockDim.x;
    for (int e = i; e < Ee; e += stride) {
        int d = dst[e], s = src[e];
        int pos = atomicAdd(&g_cursor[d], 1);
        unsigned short hb = __half_as_ushort(__float2half_rn(g_dis[s]));  // <2.0 -> fits 15 bits
        g_csrc[pos] = s | ((int)hb << 17);
        atomicAdd(&g_tsum[s], g_dis[d]);
    }
}

// fused: W1 fp16 pack + embed table
__global__ void k_prep(const float* __restrict__ W1, const float* __restrict__ embed) {
    int idx = blockIdx.x * blockDim.x + threadIdx.x;
    if (idx < 64 * Hh) {
        int kp = idx >> 7, h = idx & 127;
        int k0 = 2 * kp, k1 = 2 * kp + 1;
        float w0 = (k0 < FIN) ? W1[k0 * Hh + h] : 0.f;
        float w1 = (k1 < FIN) ? W1[k1 * Hh + h] : 0.f;
        g_W1p[kp][h] = packh(w0, w1);
    } else if (idx < 64 * Hh + 8 * Hh) {
        int j2 = idx - 64 * Hh;
        int e = j2 >> 7, h = j2 & 127;
        float s = 0.f;
        #pragma unroll
        for (int j = 0; j < EMBD; j++) s += embed[e * EMBD + j] * W1[(FIN + j) * Hh + h];
        g_T[j2] = s;
    }
}

// -------- fp16 tensor-core GEMM: 512 threads, warp tile 32x32, C=32 regs/thread --------
__global__ __launch_bounds__(512, 1) void k_gemm(const float* __restrict__ node,
                                                 const int* __restrict__ ntype) {
    __shared__ float    As[2][128][20];     // [buf][row][k] (+4 pad)
    __shared__ uint32_t Bp[2][8][136];      // [buf][kpair][h]
    int b = blockIdx.y;
    int n0 = blockIdx.x * 128;
    int t = threadIdx.x;
    int w = t >> 5, lane = t & 31;
    int wm = w & 3, wn = w >> 2;         // warp tile: rows wm*32, cols wn*32
    int g = lane >> 2, t4 = lane & 3;
    const float* Abase = node + (size_t)b * Nn * FIN;

    uint32_t sAs = (uint32_t)__cvta_generic_to_shared(&As[0][0][0]);
    uint32_t sBp = (uint32_t)__cvta_generic_to_shared(&Bp[0][0][0]);

    float C[2][4][4];
    #pragma unroll
    for (int mt = 0; mt < 2; mt++)
        #pragma unroll
        for (int nt = 0; nt < 4; nt++)
            #pragma unroll
            for (int x = 0; x < 4; x++) C[mt][nt][x] = 0.f;

    auto issue = [&](int s) {
        int buf = s & 1;
        // A: 128 rows x 4 float4 = 512 f4, 1 per thread
        {
            int row = t >> 2, c = t & 3;
            int n = n0 + row, k = s * 16 + 4 * c;
            bool ok = (n < Nn) && (k < FIN);
            const float* srcp = ok ? (Abase + (size_t)n * FIN + k) : Abase;
            cp16(sAs + (((buf * 128 + row) * 20 + 4 * c) << 2), srcp, ok);
        }
        // B: 8 kpairs x 32 f4 = 256 f4, threads 0-255
        if (t < 256) {
            int c = t & 31, kp = t >> 5;
            cp16(sBp + (((buf * 8 + kp) * 136 + 4 * c) << 2),
                 &g_W1p[s * 8 + kp][4 * c], true);
        }
    };

    issue(0);
    CP_COMMIT();

    for (int s = 0; s < NS2; s++) {
        if (s + 1 < NS2) issue(s + 1);
        CP_COMMIT();
        CP_WAIT1();
        __syncthreads();
        int buf = s & 1;

        uint32_t a[2][4];
        #pragma unroll
        for (int mt = 0; mt < 2; mt++) {
            int R = wm * 32 + mt * 16;
            float2 v0 = *(const float2*)&As[buf][R + g][2 * t4];
            float2 v1 = *(const float2*)&As[buf][R + g + 8][2 * t4];
            float2 v2 = *(const float2*)&As[buf][R + g][2 * t4 + 8];
            float2 v3 = *(const float2*)&As[buf][R + g + 8][2 * t4 + 8];
            a[mt][0] = packh(v0.x, v0.y);
            a[mt][1] = packh(v1.x, v1.y);
            a[mt][2] = packh(v2.x, v2.y);
            a[mt][3] = packh(v3.x, v3.y);
        }
        #pragma unroll
        for (int nt = 0; nt < 4; nt++) {
            int c = wn * 32 + nt * 8 + g;
            uint32_t b0 = Bp[buf][t4][c];
            uint32_t b1 = Bp[buf][t4 + 4][c];
            MMA_F16(C[0][nt], a[0], b0, b1);
            MMA_F16(C[1][nt], a[1], b0, b1);
        }
        __syncthreads();
    }

    // epilogue: add embed-table term, quantize to int8 at [n][2h+b]
    #pragma unroll
    for (int mt = 0; mt < 2; mt++) {
        int r0 = n0 + wm * 32 + mt * 16 + g;
        int r1 = r0 + 8;
        int e0 = (r0 < Nn) ? ntype[r0] : 0;
        int e1 = (r1 < Nn) ? ntype[r1] : 0;
        #pragma unroll
        for (int nt = 0; nt < 4; nt++) {
            int h = wn * 32 + nt * 8 + 2 * t4;
            if (r0 < Nn) {
                g_x8[(size_t)r0 * 256 + 2 * h + b]       = quant8(C[mt][nt][0] + g_T[e0 * Hh + h]);
                g_x8[(size_t)r0 * 256 + 2 * (h + 1) + b] = quant8(C[mt][nt][1] + g_T[e0 * Hh + h + 1]);
            }
            if (r1 < Nn) {
                g_x8[(size_t)r1 * 256 + 2 * h + b]       = quant8(C[mt][nt][2] + g_T[e1 * Hh + h]);
                g_x8[(size_t)r1 * 256 + 2 * (h + 1) + b] = quant8(C[mt][nt][3] + g_T[e1 * Hh + h + 1]);
            }
        }
    }
}

// -------- aggregation: warp-per-node, 1 LDG.64 per edge, half2 math --------
__device__ __forceinline__ void agg_edge(int2 v, __half2 W, __half2 HB, __half2 acc[4]) {
    uint32_t x0 = (uint32_t)v.x ^ 0x80808080u;
    uint32_t x1 = (uint32_t)v.y ^ 0x80808080u;
    acc[0] = __hfma2(__hsub2(u2h2(__byte_perm(x0, 0x64646464u, 0x5140)), HB), W, acc[0]);
    acc[1] = __hfma2(__hsub2(u2h2(__byte_perm(x0, 0x64646464u, 0x7362)), HB), W, acc[1]);
    acc[2] = __hfma2(__hsub2(u2h2(__byte_perm(x1, 0x64646464u, 0x5140)), HB), W, acc[2]);
    acc[3] = __hfma2(__hsub2(u2h2(__byte_perm(x1, 0x64646464u, 0x7362)), HB), W, acc[3]);
}
__device__ __forceinline__ __half2 wdec(int e) {
    return __half2half2(__ushort_as_half((unsigned short)((uint32_t)e >> 17)));
}

__global__ __launch_bounds__(128) void k_agg(const float* __restrict__ b1) {
    int w = threadIdx.x >> 5, l = threadIdx.x & 31;
    int ibase = blockIdx.x * NPB + w * 16;
    int ilim = ibase + 16; if (ilim > Nn) ilim = Nn;
    const float4 bb = ((const float4*)b1)[l];
    const __half2 HB = u2h2(0x64806480u);
    float2 facc[4] = {{0.f,0.f},{0.f,0.f},{0.f,0.f},{0.f,0.f}};

    for (int i = ibase; i < ilim; i++) {
        int beg = g_rowstart[i], end = g_rowstart[i + 1];
        __half2 acc[4];
        acc[0] = acc[1] = acc[2] = acc[3] = u2h2(0u);
        for (int c = beg; c < end; c += 32) {
            int m = end - c; if (m > 32) m = 32;
            int wd = (l < m) ? __ldg(&g_csrc[c + l]) : 0;
            int j = 0;
            for (; j + 4 <= m; j += 4) {
                int e0 = __shfl_sync(0xffffffffu, wd, j);
                int e1 = __shfl_sync(0xffffffffu, wd, j + 1);
                int e2 = __shfl_sync(0xffffffffu, wd, j + 2);
                int e3 = __shfl_sync(0xffffffffu, wd, j + 3);
                int2 v0 = __ldg((const int2*)(g_x8 + (size_t)(e0 & 0x1ffff) * 256) + l);
                int2 v1 = __ldg((const int2*)(g_x8 + (size_t)(e1 & 0x1ffff) * 256) + l);
                int2 v2 = __ldg((const int2*)(g_x8 + (size_t)(e2 & 0x1ffff) * 256) + l);
                int2 v3 = __ldg((const int2*)(g_x8 + (size_t)(e3 & 0x1ffff) * 256) + l);
                agg_edge(v0, wdec(e0), HB, acc);
                agg_edge(v1, wdec(e1), HB, acc);
                agg_edge(v2, wdec(e2), HB, acc);
                agg_edge(v3, wdec(e3), HB, acc);
            }
            for (; j < m; j++) {
                int e0 = __shfl_sync(0xffffffffu, wd, j);
                int2 v0 = __ldg((const int2*)(g_x8 + (size_t)(e0 & 0x1ffff) * 256) + l);
                agg_edge(v0, wdec(e0), HB, acc);
            }
        }
        // self term + epilogue
        int2 vs = __ldg((const int2*)(g_x8 + (size_t)i * 256) + l);
        __half2 sf[4];
        sf[0] = sf[1] = sf[2] = sf[3] = u2h2(0u);
        agg_edge(vs, __float2half2_rn(1.0f), HB, sf);
        float d = g_dis[i];
        float sI = d * (g_tsum[i] + d);
        float qd = QINV * d;
        const float* bbp = (const float*)&bb;
        #pragma unroll
        for (int k = 0; k < 4; k++) {
            float2 a2 = __half22float2(acc[k]);
            float2 s2 = __half22float2(sf[k]);
            float h0 = fmaxf(fmaf(qd, a2.x + d * s2.x, bbp[k]), 0.f);
            float h1 = fmaxf(fmaf(qd, a2.y + d * s2.y, bbp[k]), 0.f);
            facc[k].x += sI * h0;
            facc[k].y += sI * h1;
        }
    }
    int ci = ((blockIdx.x << 2) + w) & (NC - 1);
    float* dstp = g_acc + ci * 256;
    #pragma unroll
    for (int k = 0; k < 4; k++) {
        atomicAdd(dstp + 4 * l + k, facc[k].x);
        atomicAdd(dstp + 128 + 4 * l + k, facc[k].y);
    }
}

// -------- final: out[b][h2] = b2 + (1/N) * v[b] @ W2 --------
__global__ void k_final(const float* __restrict__ W2, const float* __restrict__ b2,
                        float* __restrict__ out) {
    __shared__ float v[256];
    int t = threadIdx.x;
    float s = 0.f;
    for (int c = 0; c < NC; c++) s += g_acc[c * 256 + t];
    v[t] = s * (1.0f / (float)Nn);
    __syncthreads();
    int b = t >> 7, h2 = t & 127;
    float o = b2[h2];
    for (int f = 0; f < 128; f++) o += v[b * 128 + f] * W2[f * Hh + h2];
    out[b * Hh + h2] = o;
}

extern "C" void kernel_launch(void* const* d_in, const int* in_sizes, int n_in,
                              void* d_out, int out_size) {
    const float* node  = (const float*)d_in[0];
    const int*   ntype = (const int*)d_in[1];
    const int*   ei    = (const int*)d_in[2];
    const float* embed = (const float*)d_in[3];
    const float* W1    = (const float*)d_in[4];
    const float* b1    = (const float*)d_in[5];
    const float* W2    = (const float*)d_in[6];
    const float* b2    = (const float*)d_in[7];
    const int* src = ei;
    const int* dst = ei + Ee;

    // fork: side branch runs W1 prep + GEMM concurrently with the CSR build chain
    cudaEventRecord(g_e0, 0);
    cudaStreamWaitEvent(g_s2, g_e0, 0);

    // side branch (independent of edges)
    k_prep<<<(64 * Hh + 8 * Hh + 255) / 256, 256, 0, g_s2>>>(W1, embed);
    k_gemm<<<dim3((Nn + 127) / 128, Bb), 512, 0, g_s2>>>(node, ntype);
    cudaEventRecord(g_e1, g_s2);

    // main branch: CSR build
    k_zero<<<256, 256>>>();
    k_hist<<<1024, 256>>>(dst);
    k_scanA<<<NSB, 1024>>>();
    k_scanB<<<1, 32>>>();
    k_scanC<<<NSB, 1024>>>();
    k_scatter<<<1024, 256>>>(src, dst);

    // join, then aggregate + finalize
    cudaStreamWaitEvent(0, g_e1, 0);
    k_agg<<<(Nn + NPB - 1) / NPB, 128>>>(b1);
    k_final<<<1, 256>>>(W2, b2, (float*)d_out);
}

// round 16
// speedup vs baseline: 1.1262x; 1.1262x over previous
#include <cuda_runtime.h>
#include <cuda_fp16.h>
#include <cstdint>

#define Nn   100000
#define Ee   1600000
#define Bb   2
#define FIN  116
#define EMBD 12
#define Hh   128
#define NS2  8           // K chunks of 16 (K padded to 128)
#define NC   128         // accumulator copies
#define NPB  64          // nodes per agg block (16 per warp)
#define NSB  98          // scan blocks (ceil(100000/1024))

#define QSCALE (127.0f / 8.0f)
#define QINV   (8.0f / 127.0f)

// -------- scratch (static device globals) --------
__device__ char  g_x8[(size_t)Nn * 256];   // [n][2h+b] int8 quantized xw1: 25.6 MB
__device__ int   g_cnt[Nn];
__device__ int   g_cursor[Nn];
__device__ float g_dis[Nn];
__device__ float g_tsum[Nn];
__device__ int   g_rowstart[Nn + 1];
__device__ int   g_bsum[NSB];
__device__ int   g_csrc[Ee];               // bits[0:17)=src, bits[17:32)=fp16 bits of dis[src]
__device__ float g_T[8 * Hh];
__device__ float g_acc[NC * 256];
__device__ uint32_t g_W1p[64][Hh];         // [kpair][h] fp16x2 packed (low half = even k)

// -------- host-side stream/event resources (created once at load; no device alloc) --------
static cudaStream_t g_s2;
static cudaEvent_t  g_e0, g_e1;
static struct SideStreamInit {
    SideStreamInit() {
        cudaStreamCreateWithFlags(&g_s2, cudaStreamNonBlocking);
        cudaEventCreateWithFlags(&g_e0, cudaEventDisableTiming);
        cudaEventCreateWithFlags(&g_e1, cudaEventDisableTiming);
    }
} g_ssi;

// -------- small helpers --------
__device__ __forceinline__ uint32_t packh(float lo, float hi) {
    __half2 h = __floats2half2_rn(lo, hi);
    return *(uint32_t*)&h;
}
__device__ __forceinline__ void cp16(uint32_t dst, const void* src, bool pred) {
    int sz = pred ? 16 : 0;
    asm volatile("cp.async.cg.shared.global [%0], [%1], 16, %2;\n" :: "r"(dst), "l"(src), "r"(sz));
}
#define CP_COMMIT() asm volatile("cp.async.commit_group;\n" ::: "memory")
#define CP_WAIT1()  asm volatile("cp.async.wait_group 1;\n" ::: "memory")

#define MMA_F16(Cr, Ar, B0, B1)                                               \
    asm volatile("mma.sync.aligned.m16n8k16.row.col.f32.f16.f16.f32 "         \
                 "{%0,%1,%2,%3},{%4,%5,%6,%7},{%8,%9},{%0,%1,%2,%3};"         \
                 : "+f"(Cr[0]), "+f"(Cr[1]), "+f"(Cr[2]), "+f"(Cr[3])         \
                 : "r"(Ar[0]), "r"(Ar[1]), "r"(Ar[2]), "r"(Ar[3]),            \
                   "r"(B0), "r"(B1))

__device__ __forceinline__ char quant8(float v) {
    int q = __float2int_rn(v * QSCALE);
    q = max(-127, min(127, q));
    return (char)q;
}
__device__ __forceinline__ __half2 u2h2(uint32_t u) {
    __half2_raw r; r.x = (unsigned short)(u & 0xffff); r.y = (unsigned short)(u >> 16);
    return r;
}

// -------- prep kernels --------
__global__ void k_zero() {
    int i = blockIdx.x * blockDim.x + threadIdx.x;
    int stride = gridDim.x * blockDim.x;
    for (int j = i; j < Nn; j += stride) g_cnt[j] = 0;
    for (int j = i; j < NC * 256; j += stride) g_acc[j] = 0.f;
}

__global__ void k_hist(const int* __restrict__ dst) {
    int i = blockIdx.x * blockDim.x + threadIdx.x;
    int stride = gridDim.x * blockDim.x;
    for (int e = i; e < Ee; e += stride) atomicAdd(&g_cnt[dst[e]], 1);
}

// ---- 3-phase parallel scan; A computes dis and zeroes tsum; C also seeds cursor ----
__global__ void k_scanA() {
    __shared__ int sd[1024];
    int t = threadIdx.x;
    int idx = blockIdx.x * 1024 + t;
    int v = (idx < Nn) ? g_cnt[idx] : 0;
    sd[t] = v;
    __syncthreads();
    for (int off = 1; off < 1024; off <<= 1) {
        int x = (t >= off) ? sd[t - off] : 0;
        __syncthreads();
        sd[t] += x;
        __syncthreads();
    }
    if (idx < Nn) {
        g_rowstart[idx] = sd[t] - v;   // block-local exclusive
        g_dis[idx] = rsqrtf((float)v + 1.0f);
        g_tsum[idx] = 0.f;
    }
    if (t == 1023) g_bsum[blockIdx.x] = sd[1023];
}

__global__ void k_scanB() {
    int l = threadIdx.x;   // 32 threads
    int base = 4 * l;
    int v0 = (base + 0 < NSB) ? g_bsum[base + 0] : 0;
    int v1 = (base + 1 < NSB) ? g_bsum[base + 1] : 0;
    int v2 = (base + 2 < NSB) ? g_bsum[base + 2] : 0;
    int v3 = (base + 3 < NSB) ? g_bsum[base + 3] : 0;
    int t0 = v0, t1 = t0 + v1, t2 = t1 + v2, tot = t2 + v3;
    int incl = tot;
    #pragma unroll
    for (int off = 1; off < 32; off <<= 1) {
        int y = __shfl_up_sync(0xffffffffu, incl, off);
        if (l >= off) incl += y;
    }
    int excl = incl - tot;
    if (base + 0 < NSB) g_bsum[base + 0] = excl;
    if (base + 1 < NSB) g_bsum[base + 1] = excl + t0;
    if (base + 2 < NSB) g_bsum[base + 2] = excl + t1;
    if (base + 3 < NSB) g_bsum[base + 3] = excl + t2;
    if (l == 31) g_rowstart[Nn] = incl;
}

__global__ void k_scanC() {
    int t = threadIdx.x;
    int idx = blockIdx.x * 1024 + t;
    if (idx < Nn) {
        int rs = g_rowstart[idx] + g_bsum[blockIdx.x];
        g_rowstart[idx] = rs;
        g_cursor[idx] = rs;     // scatter bumps cursor directly
    }
}

// scatter CSR col (src + fp16 dis[src] in top 15 bits) + fused tsum accumulation
__global__ void k_scatter(const int* __restrict__ src, const int* __restrict__ dst) {
    int i = blockIdx.x * blockDim.x + threadIdx.x;
    int stride = gridDim.x * blockDim.x;
    for (int e = i; e < Ee; e += stride) {
        int d = dst[e], s = src[e];
        int pos = atomicAdd(&g_cursor[d], 1);
        unsigned short hb = __half_as_ushort(__float2half_rn(g_dis[s]));  // <2.0 -> fits 15 bits
        g_csrc[pos] = s | ((int)hb << 17);
        atomicAdd(&g_tsum[s], g_dis[d]);
    }
}

// fused: W1 fp16 pack + embed table
__global__ void k_prep(const float* __restrict__ W1, const float* __restrict__ embed) {
    int idx = blockIdx.x * blockDim.x + threadIdx.x;
    if (idx < 64 * Hh) {
        int kp = idx >> 7, h = idx & 127;
        int k0 = 2 * kp, k1 = 2 * kp + 1;
        float w0 = (k0 < FIN) ? W1[k0 * Hh + h] : 0.f;
        float w1 = (k1 < FIN) ? W1[k1 * Hh + h] : 0.f;
        g_W1p[kp][h] = packh(w0, w1);
    } else if (idx < 64 * Hh + 8 * Hh) {
        int j2 = idx - 64 * Hh;
        int e = j2 >> 7, h = j2 & 127;
        float s = 0.f;
        #pragma unroll
        for (int j = 0; j < EMBD; j++) s += embed[e * EMBD + j] * W1[(FIN + j) * Hh + h];
        g_T[j2] = s;
    }
}

// -------- fp16 tensor-core GEMM: 256 threads, occ 2, warp tile 32x64 (R13 config) --------
__global__ __launch_bounds__(256, 2) void k_gemm(const float* __restrict__ node,
                                                 const int* __restrict__ ntype) {
    __shared__ float    As[2][128][20];     // [buf][row][k] (+4 pad)
    __shared__ uint32_t Bp[2][8][136];      // [buf][kpair][h]
    int b = blockIdx.y;
    int n0 = blockIdx.x * 128;
    int t = threadIdx.x;
    int w = t >> 5, lane = t & 31;
    int wm = w & 3, wn = w >> 2;         // warp tile: rows wm*32, cols wn*64
    int g = lane >> 2, t4 = lane & 3;
    const float* Abase = node + (size_t)b * Nn * FIN;

    uint32_t sAs = (uint32_t)__cvta_generic_to_shared(&As[0][0][0]);
    uint32_t sBp = (uint32_t)__cvta_generic_to_shared(&Bp[0][0][0]);

    float C[2][8][4];
    #pragma unroll
    for (int mt = 0; mt < 2; mt++)
        #pragma unroll
        for (int nt = 0; nt < 8; nt++)
            #pragma unroll
            for (int x = 0; x < 4; x++) C[mt][nt][x] = 0.f;

    auto issue = [&](int s) {
        int buf = s & 1;
        // A: 128 rows x 4 float4 = 512 f4, 2 per thread
        #pragma unroll
        for (int i = 0; i < 2; i++) {
            int lin = i * 256 + t;
            int row = lin >> 2, c = lin & 3;
            int n = n0 + row, k = s * 16 + 4 * c;
            bool ok = (n < Nn) && (k < FIN);
            const float* srcp = ok ? (Abase + (size_t)n * FIN + k) : Abase;
            cp16(sAs + (((buf * 128 + row) * 20 + 4 * c) << 2), srcp, ok);
        }
        // B: 8 kpairs x 32 f4 = 256 f4, 1 per thread
        {
            int c = t & 31, kp = (t >> 5) & 7;
            cp16(sBp + (((buf * 8 + kp) * 136 + 4 * c) << 2),
                 &g_W1p[s * 8 + kp][4 * c], true);
        }
    };

    issue(0);
    CP_COMMIT();

    for (int s = 0; s < NS2; s++) {
        if (s + 1 < NS2) issue(s + 1);
        CP_COMMIT();
        CP_WAIT1();
        __syncthreads();
        int buf = s & 1;

        uint32_t a[2][4];
        #pragma unroll
        for (int mt = 0; mt < 2; mt++) {
            int R = wm * 32 + mt * 16;
            float2 v0 = *(const float2*)&As[buf][R + g][2 * t4];
            float2 v1 = *(const float2*)&As[buf][R + g + 8][2 * t4];
            float2 v2 = *(const float2*)&As[buf][R + g][2 * t4 + 8];
            float2 v3 = *(const float2*)&As[buf][R + g + 8][2 * t4 + 8];
            a[mt][0] = packh(v0.x, v0.y);
            a[mt][1] = packh(v1.x, v1.y);
            a[mt][2] = packh(v2.x, v2.y);
            a[mt][3] = packh(v3.x, v3.y);
        }
        #pragma unroll
        for (int nt = 0; nt < 8; nt++) {
            int c = wn * 64 + nt * 8 + g;
            uint32_t b0 = Bp[buf][t4][c];
            uint32_t b1 = Bp[buf][t4 + 4][c];
            MMA_F16(C[0][nt], a[0], b0, b1);
            MMA_F16(C[1][nt], a[1], b0, b1);
        }
        __syncthreads();
    }

    // epilogue: add embed-table term, quantize to int8 at [n][2h+b]
    #pragma unroll
    for (int mt = 0; mt < 2; mt++) {
        int r0 = n0 + wm * 32 + mt * 16 + g;
        int r1 = r0 + 8;
        int e0 = (r0 < Nn) ? ntype[r0] : 0;
        int e1 = (r1 < Nn) ? ntype[r1] : 0;
        #pragma unroll
        for (int nt = 0; nt < 8; nt++) {
            int h = wn * 64 + nt * 8 + 2 * t4;
            if (r0 < Nn) {
                g_x8[(size_t)r0 * 256 + 2 * h + b]       = quant8(C[mt][nt][0] + g_T[e0 * Hh + h]);
                g_x8[(size_t)r0 * 256 + 2 * (h + 1) + b] = quant8(C[mt][nt][1] + g_T[e0 * Hh + h + 1]);
            }
            if (r1 < Nn) {
                g_x8[(size_t)r1 * 256 + 2 * h + b]       = quant8(C[mt][nt][2] + g_T[e1 * Hh + h]);
                g_x8[(size_t)r1 * 256 + 2 * (h + 1) + b] = quant8(C[mt][nt][3] + g_T[e1 * Hh + h + 1]);
            }
        }
    }
}

// -------- aggregation: warp-per-node, 1 LDG.64 per edge, half2 math --------
__device__ __forceinline__ void agg_edge(int2 v, __half2 W, __half2 HB, __half2 acc[4]) {
    uint32_t x0 = (uint32_t)v.x ^ 0x80808080u;
    uint32_t x1 = (uint32_t)v.y ^ 0x80808080u;
    acc[0] = __hfma2(__hsub2(u2h2(__byte_perm(x0, 0x64646464u, 0x5140)), HB), W, acc[0]);
    acc[1] = __hfma2(__hsub2(u2h2(__byte_perm(x0, 0x64646464u, 0x7362)), HB), W, acc[1]);
    acc[2] = __hfma2(__hsub2(u2h2(__byte_perm(x1, 0x64646464u, 0x5140)), HB), W, acc[2]);
    acc[3] = __hfma2(__hsub2(u2h2(__byte_perm(x1, 0x64646464u, 0x7362)), HB), W, acc[3]);
}
__device__ __forceinline__ __half2 wdec(int e) {
    return __half2half2(__ushort_as_half((unsigned short)((uint32_t)e >> 17)));
}

__global__ __launch_bounds__(128) void k_agg(const float* __restrict__ b1) {
    int w = threadIdx.x >> 5, l = threadIdx.x & 31;
    int ibase = blockIdx.x * NPB + w * 16;
    int ilim = ibase + 16; if (ilim > Nn) ilim = Nn;
    const float4 bb = ((const float4*)b1)[l];
    const __half2 HB = u2h2(0x64806480u);
    float2 facc[4] = {{0.f,0.f},{0.f,0.f},{0.f,0.f},{0.f,0.f}};

    for (int i = ibase; i < ilim; i++) {
        int beg = g_rowstart[i], end = g_rowstart[i + 1];
        __half2 acc[4];
        acc[0] = acc[1] = acc[2] = acc[3] = u2h2(0u);
        for (int c = beg; c < end; c += 32) {
            int m = end - c; if (m > 32) m = 32;
            int wd = (l < m) ? __ldg(&g_csrc[c + l]) : 0;
            int j = 0;
            for (; j + 4 <= m; j += 4) {
                int e0 = __shfl_sync(0xffffffffu, wd, j);
                int e1 = __shfl_sync(0xffffffffu, wd, j + 1);
                int e2 = __shfl_sync(0xffffffffu, wd, j + 2);
                int e3 = __shfl_sync(0xffffffffu, wd, j + 3);
                int2 v0 = __ldg((const int2*)(g_x8 + (size_t)(e0 & 0x1ffff) * 256) + l);
                int2 v1 = __ldg((const int2*)(g_x8 + (size_t)(e1 & 0x1ffff) * 256) + l);
                int2 v2 = __ldg((const int2*)(g_x8 + (size_t)(e2 & 0x1ffff) * 256) + l);
                int2 v3 = __ldg((const int2*)(g_x8 + (size_t)(e3 & 0x1ffff) * 256) + l);
                agg_edge(v0, wdec(e0), HB, acc);
                agg_edge(v1, wdec(e1), HB, acc);
                agg_edge(v2, wdec(e2), HB, acc);
                agg_edge(v3, wdec(e3), HB, acc);
            }
            for (; j < m; j++) {
                int e0 = __shfl_sync(0xffffffffu, wd, j);
                int2 v0 = __ldg((const int2*)(g_x8 + (size_t)(e0 & 0x1ffff) * 256) + l);
                agg_edge(v0, wdec(e0), HB, acc);
            }
        }
        // self term + epilogue
        int2 vs = __ldg((const int2*)(g_x8 + (size_t)i * 256) + l);
        __half2 sf[4];
        sf[0] = sf[1] = sf[2] = sf[3] = u2h2(0u);
        agg_edge(vs, __float2half2_rn(1.0f), HB, sf);
        float d = g_dis[i];
        float sI = d * (g_tsum[i] + d);
        float qd = QINV * d;
        const float* bbp = (const float*)&bb;
        #pragma unroll
        for (int k = 0; k < 4; k++) {
            float2 a2 = __half22float2(acc[k]);
            float2 s2 = __half22float2(sf[k]);
            float h0 = fmaxf(fmaf(qd, a2.x + d * s2.x, bbp[k]), 0.f);
            float h1 = fmaxf(fmaf(qd, a2.y + d * s2.y, bbp[k]), 0.f);
            facc[k].x += sI * h0;
            facc[k].y += sI * h1;
        }
    }
    int ci = ((blockIdx.x << 2) + w) & (NC - 1);
    float* dstp = g_acc + ci * 256;
    #pragma unroll
    for (int k = 0; k < 4; k++) {
        atomicAdd(dstp + 4 * l + k, facc[k].x);
        atomicAdd(dstp + 128 + 4 * l + k, facc[k].y);
    }
}

// -------- final: out[b][h2] = b2 + (1/N) * v[b] @ W2 --------
__global__ void k_final(const float* __restrict__ W2, const float* __restrict__ b2,
                        float* __restrict__ out) {
    __shared__ float v[256];
    int t = threadIdx.x;
    float s = 0.f;
    for (int c = 0; c < NC; c++) s += g_acc[c * 256 + t];
    v[t] = s * (1.0f / (float)Nn);
    __syncthreads();
    int b = t >> 7, h2 = t & 127;
    float o = b2[h2];
    for (int f = 0; f < 128; f++) o += v[b * 128 + f] * W2[f * Hh + h2];
    out[b * Hh + h2] = o;
}

extern "C" void kernel_launch(void* const* d_in, const int* in_sizes, int n_in,
                              void* d_out, int out_size) {
    const float* node  = (const float*)d_in[0];
    const int*   ntype = (const int*)d_in[1];
    const int*   ei    = (const int*)d_in[2];
    const float* embed = (const float*)d_in[3];
    const float* W1    = (const float*)d_in[4];
    const float* b1    = (const float*)d_in[5];
    const float* W2    = (const float*)d_in[6];
    const float* b2    = (const float*)d_in[7];
    const int* src = ei;
    const int* dst = ei + Ee;

    // fork: side branch runs W1 prep + GEMM concurrently with the CSR build chain
    cudaEventRecord(g_e0, 0);
    cudaStreamWaitEvent(g_s2, g_e0, 0);

    // side branch (independent of edges)
    k_prep<<<(64 * Hh + 8 * Hh + 255) / 256, 256, 0, g_s2>>>(W1, embed);
    k_gemm<<<dim3((Nn + 127) / 128, Bb), 256, 0, g_s2>>>(node, ntype);
    cudaEventRecord(g_e1, g_s2);

    // main branch: CSR build
    k_zero<<<256, 256>>>();
    k_hist<<<1024, 256>>>(dst);
    k_scanA<<<NSB, 1024>>>();
    k_scanB<<<1, 32>>>();
    k_scanC<<<NSB, 1024>>>();
    k_scatter<<<1024, 256>>>(src, dst);

    // join, then aggregate + finalize
    cudaStreamWaitEvent(0, g_e1, 0);
    k_agg<<<(Nn + NPB - 1) / NPB, 128>>>(b1);
    k_final<<<1, 256>>>(W2, b2, (float*)d_out);
}